// round 8
// baseline (speedup 1.0000x reference)
#include <cuda_runtime.h>
#include <cuda_bf16.h>
#include <stdint.h>

#define BATCH   2048
#define N0      49
#define CH      768
#define MID     48
#define K1      36
#define K2      24
#define THREADS 960
#define WARPS   30
#define NC4     192          /* float4 columns */

// Preprocessed weights (device globals).
//   g_w1t[r][j*CH + c]  = bf16( se{r}_w1[c, j] )   transposed GEMV rows
//   g_w2t[r][c*MID + j] = bf16( se{r}_w2[j, c] )   per-thread contiguous
//   g_clsu[o*CH + c]    = ln_gamma[c] * cls_w[c, o]
//   g_clsA[o] = sum_c gamma[c]*w[c,o];  g_clsB[o] = sum_c beta[c]*w[c,o] + cls_b[o]
__device__ __nv_bfloat16 g_w1t[2][MID * CH];
__device__ __nv_bfloat16 g_w2t[2][MID * CH];
__device__ float         g_clsu[5 * CH];
__device__ float         g_clsA[5];
__device__ float         g_clsB[5];

__global__ void convert_weights_kernel(const float* __restrict__ w1a,
                                       const float* __restrict__ w2a,
                                       const float* __restrict__ w1b,
                                       const float* __restrict__ w2b,
                                       const float* __restrict__ clsw,
                                       const float* __restrict__ lng,
                                       const float* __restrict__ lnb,
                                       const float* __restrict__ clsb) {
    int i = blockIdx.x * blockDim.x + threadIdx.x;
    if (i < MID * CH) {
        int j = i / CH;
        int c = i - j * CH;
        g_w1t[0][i] = __float2bfloat16(w1a[c * MID + j]);
        g_w1t[1][i] = __float2bfloat16(w1b[c * MID + j]);
        g_w2t[0][c * MID + j] = __float2bfloat16(w2a[j * CH + c]);
        g_w2t[1][c * MID + j] = __float2bfloat16(w2b[j * CH + c]);
    }
    if (i < 5 * CH) {
        int o = i / CH;
        int c = i - o * CH;
        g_clsu[i] = lng[c] * clsw[c * 5 + o];
    }
    if (i < 5) {
        float A = 0.f, Bv = 0.f;
        for (int c = 0; c < CH; c++) {
            A  += lng[c] * clsw[c * 5 + i];
            Bv += lnb[c] * clsw[c * 5 + i];
        }
        g_clsA[i] = A;
        g_clsB[i] = Bv + clsb[i];
    }
}

// Shared memory (floats):
//   tile[N0*CH]   raw x fp32 (read-only after load)
//   part[5*CH]    load-time column partials
//   sbuf[CH]      colmean / s2 / pooled
//   csum[CH]      running column sum (complement trick)
//   gat [CH]      cumulative gate product
//   hbuf[MID], ts[64], xfin[8], list[40] int, uns[16] int, uns2[16] int
#define SM_FLOATS (N0*CH + 5*CH + CH + CH + CH + MID + 64 + 8 + 40 + 16 + 16)
#define SM_BYTES  (SM_FLOATS * 4)

__global__ __launch_bounds__(THREADS, 1)
void coatgft_kernel(const float* __restrict__ x,
                    const float* __restrict__ b1a, const float* __restrict__ b2a,
                    const float* __restrict__ b1b, const float* __restrict__ b2b,
                    float* __restrict__ out) {
    extern __shared__ float sm[];
    float* tile = sm;                    // [N0*CH]
    float* part = tile + N0 * CH;        // [5*CH]
    float* sbuf = part + 5 * CH;         // [CH]
    float* csum = sbuf + CH;             // [CH]
    float* gat  = csum + CH;             // [CH]
    float* hbuf = gat + CH;              // [MID]
    float* ts   = hbuf + MID;            // [64]
    float* xfin = ts + 64;               // [8]
    int*   list = (int*)(xfin + 8);      // [40]
    int*   uns  = list + 40;             // [16]
    int*   uns2 = uns + 16;              // [16]

    const int tid  = threadIdx.x;
    const int lane = tid & 31;
    const int warp = tid >> 5;
    const int b    = blockIdx.x;

    // ---------- fused load + round-1 column partial sums ----------
    {
        const float* xb = x + (size_t)b * N0 * CH;
        const int c4 = tid % NC4;        // float4 column 0..191
        const int rb = tid / NC4;        // row group 0..4
        float4 acc = make_float4(0.f, 0.f, 0.f, 0.f);
        #pragma unroll
        for (int k = 0; k < 10; k++) {
            int r = rb + 5 * k;
            if (r < N0) {
                float4 v = *(const float4*)(xb + (size_t)r * CH + 4 * c4);
                *(float4*)(tile + r * CH + 4 * c4) = v;
                acc.x += v.x; acc.y += v.y; acc.z += v.z; acc.w += v.w;
            }
        }
        *(float4*)(part + rb * CH + 4 * c4) = acc;
    }
    __syncthreads();
    if (tid < CH) {
        float cs = part[tid] + part[CH + tid] + part[2 * CH + tid]
                 + part[3 * CH + tid] + part[4 * CH + tid];
        csum[tid] = cs;
        sbuf[tid] = cs * (1.0f / (float)N0);   // colmean49
    }
    __syncthreads();

    // ================= ROUND 1 =================
    {   // h = gelu(s @ W1 + b1): up to 2 outputs per warp, gelu fused
        const __nv_bfloat162* W1t = (const __nv_bfloat162*)g_w1t[0];
        #pragma unroll
        for (int jj = 0; jj < 2; jj++) {
            int j = warp + jj * WARPS;
            if (j < MID) {
                const __nv_bfloat162* wr = W1t + j * (CH / 2);
                float acc = 0.f;
                #pragma unroll
                for (int k = 0; k < CH / 64; k++) {
                    int p = lane + 32 * k;
                    __nv_bfloat162 w = wr[p];
                    acc += sbuf[2 * p] * __low2float(w) + sbuf[2 * p + 1] * __high2float(w);
                }
                #pragma unroll
                for (int o = 16; o; o >>= 1) acc += __shfl_xor_sync(0xffffffffu, acc, o);
                if (lane == 0) {
                    float z = acc + b1a[j];
                    hbuf[j] = 0.5f * z * (1.0f + erff(z * 0.70710678118654752f));
                }
            }
        }
    }
    __syncthreads();

    // gates1: per-thread contiguous transposed W2
    if (tid < CH) {
        const __nv_bfloat162* w = (const __nv_bfloat162*)(g_w2t[0] + (size_t)tid * MID);
        float acc = b2a[tid];
        #pragma unroll
        for (int m = 0; m < MID / 2; m++) {
            __nv_bfloat162 wv = w[m];
            acc += hbuf[2 * m] * __low2float(wv) + hbuf[2 * m + 1] * __high2float(wv);
        }
        gat[tid] = 1.0f / (1.0f + expf(-acc));
    }
    __syncthreads();

    // ts1[r] = sum_c (x*g)^2  — gates in registers, float4 tile reads
    {
        const float4* g4p = (const float4*)gat;
        float4 g0 = g4p[lane], g1 = g4p[lane + 32], g2 = g4p[lane + 64],
               g3 = g4p[lane + 96], g4 = g4p[lane + 128], g5 = g4p[lane + 160];
        #pragma unroll
        for (int ii = 0; ii < 2; ii++) {
            int r = warp + ii * WARPS;
            if (r < N0) {
                const float4* row = (const float4*)(tile + r * CH);
                float acc = 0.f, v;
                float4 a;
                a = row[lane];
                v = a.x*g0.x; acc += v*v; v = a.y*g0.y; acc += v*v;
                v = a.z*g0.z; acc += v*v; v = a.w*g0.w; acc += v*v;
                a = row[lane + 32];
                v = a.x*g1.x; acc += v*v; v = a.y*g1.y; acc += v*v;
                v = a.z*g1.z; acc += v*v; v = a.w*g1.w; acc += v*v;
                a = row[lane + 64];
                v = a.x*g2.x; acc += v*v; v = a.y*g2.y; acc += v*v;
                v = a.z*g2.z; acc += v*v; v = a.w*g2.w; acc += v*v;
                a = row[lane + 96];
                v = a.x*g3.x; acc += v*v; v = a.y*g3.y; acc += v*v;
                v = a.z*g3.z; acc += v*v; v = a.w*g3.w; acc += v*v;
                a = row[lane + 128];
                v = a.x*g4.x; acc += v*v; v = a.y*g4.y; acc += v*v;
                v = a.z*g4.z; acc += v*v; v = a.w*g4.w; acc += v*v;
                a = row[lane + 160];
                v = a.x*g5.x; acc += v*v; v = a.y*g5.y; acc += v*v;
                v = a.z*g5.z; acc += v*v; v = a.w*g5.w; acc += v*v;
                #pragma unroll
                for (int o = 16; o; o >>= 1) acc += __shfl_xor_sync(0xffffffffu, acc, o);
                if (lane == 0) ts[r] = acc;
            }
        }
    }
    __syncthreads();

    // rank-select top-36 (== jax top_k order); record 13 unselected
    if (tid < N0) {
        float mine = ts[tid];
        int r = 0;
        #pragma unroll
        for (int j = 0; j < N0; j++) {
            float tj = ts[j];
            r += (tj > mine) || (tj == mine && j < tid);
        }
        if (r < K1) list[r] = tid;
        else        uns[r - K1] = tid;
    }
    __syncthreads();

    // ================= ROUND 2 =================
    // csum36 = csum49 - 13 unselected rows; s2 = gat * csum36 / 36
    if (tid < CH) {
        float cs = csum[tid];
        #pragma unroll
        for (int i = 0; i < N0 - K1; i++) cs -= tile[uns[i] * CH + tid];
        csum[tid] = cs;
        sbuf[tid] = cs * gat[tid] * (1.0f / (float)K1);
    }
    __syncthreads();

    {
        const __nv_bfloat162* W1t = (const __nv_bfloat162*)g_w1t[1];
        #pragma unroll
        for (int jj = 0; jj < 2; jj++) {
            int j = warp + jj * WARPS;
            if (j < MID) {
                const __nv_bfloat162* wr = W1t + j * (CH / 2);
                float acc = 0.f;
                #pragma unroll
                for (int k = 0; k < CH / 64; k++) {
                    int p = lane + 32 * k;
                    __nv_bfloat162 w = wr[p];
                    acc += sbuf[2 * p] * __low2float(w) + sbuf[2 * p + 1] * __high2float(w);
                }
                #pragma unroll
                for (int o = 16; o; o >>= 1) acc += __shfl_xor_sync(0xffffffffu, acc, o);
                if (lane == 0) {
                    float z = acc + b1b[j];
                    hbuf[j] = 0.5f * z * (1.0f + erff(z * 0.70710678118654752f));
                }
            }
        }
    }
    __syncthreads();

    if (tid < CH) {
        const __nv_bfloat162* w = (const __nv_bfloat162*)(g_w2t[1] + (size_t)tid * MID);
        float acc = b2b[tid];
        #pragma unroll
        for (int m = 0; m < MID / 2; m++) {
            __nv_bfloat162 wv = w[m];
            acc += hbuf[2 * m] * __low2float(wv) + hbuf[2 * m + 1] * __high2float(wv);
        }
        gat[tid] *= 1.0f / (1.0f + expf(-acc));   // cumulative gate
    }
    __syncthreads();

    // ts2 over the 36 selected rows (cumulative gate)
    {
        const float4* g4p = (const float4*)gat;
        float4 g0 = g4p[lane], g1 = g4p[lane + 32], g2 = g4p[lane + 64],
               g3 = g4p[lane + 96], g4 = g4p[lane + 128], g5 = g4p[lane + 160];
        #pragma unroll
        for (int ii = 0; ii < 2; ii++) {
            int i = warp + ii * WARPS;
            if (i < K1) {
                const float4* row = (const float4*)(tile + list[i] * CH);
                float acc = 0.f, v;
                float4 a;
                a = row[lane];
                v = a.x*g0.x; acc += v*v; v = a.y*g0.y; acc += v*v;
                v = a.z*g0.z; acc += v*v; v = a.w*g0.w; acc += v*v;
                a = row[lane + 32];
                v = a.x*g1.x; acc += v*v; v = a.y*g1.y; acc += v*v;
                v = a.z*g1.z; acc += v*v; v = a.w*g1.w; acc += v*v;
                a = row[lane + 64];
                v = a.x*g2.x; acc += v*v; v = a.y*g2.y; acc += v*v;
                v = a.z*g2.z; acc += v*v; v = a.w*g2.w; acc += v*v;
                a = row[lane + 96];
                v = a.x*g3.x; acc += v*v; v = a.y*g3.y; acc += v*v;
                v = a.z*g3.z; acc += v*v; v = a.w*g3.w; acc += v*v;
                a = row[lane + 128];
                v = a.x*g4.x; acc += v*v; v = a.y*g4.y; acc += v*v;
                v = a.z*g4.z; acc += v*v; v = a.w*g4.w; acc += v*v;
                a = row[lane + 160];
                v = a.x*g5.x; acc += v*v; v = a.y*g5.y; acc += v*v;
                v = a.z*g5.z; acc += v*v; v = a.w*g5.w; acc += v*v;
                #pragma unroll
                for (int o = 16; o; o >>= 1) acc += __shfl_xor_sync(0xffffffffu, acc, o);
                if (lane == 0) ts[i] = acc;
            }
        }
    }
    __syncthreads();

    // select top-24 of 36: record the 12 removed rows
    if (tid < K1) {
        float mine = ts[tid];
        int r = 0;
        int row = list[tid];
        #pragma unroll
        for (int j = 0; j < K1; j++) {
            float tj = ts[j];
            r += (tj > mine) || (tj == mine && j < tid);
        }
        if (r >= K2) uns2[r - K2] = row;
    }
    __syncthreads();

    // pooled = gat * (csum36 - 12 removed rows) / 24
    if (tid < CH) {
        float cs = csum[tid];
        #pragma unroll
        for (int i = 0; i < K1 - K2; i++) cs -= tile[uns2[i] * CH + tid];
        sbuf[tid] = cs * gat[tid] * (1.0f / (float)K2);
    }
    __syncthreads();

    // fused LN+classifier: 7 warp reductions (D0..D4, S1, S2)
    if (warp < 7) {
        float acc = 0.f;
        if (warp < 5) {
            const float* u = g_clsu + warp * CH;
            #pragma unroll
            for (int k = 0; k < CH / 32; k++)
                acc += sbuf[lane + 32 * k] * u[lane + 32 * k];
        } else if (warp == 5) {
            #pragma unroll
            for (int k = 0; k < CH / 32; k++)
                acc += sbuf[lane + 32 * k];
        } else {
            #pragma unroll
            for (int k = 0; k < CH / 32; k++) {
                float v = sbuf[lane + 32 * k];
                acc += v * v;
            }
        }
        #pragma unroll
        for (int o = 16; o; o >>= 1) acc += __shfl_xor_sync(0xffffffffu, acc, o);
        if (lane == 0) xfin[warp] = acc;
    }
    __syncthreads();
    if (tid < 5) {
        float mu  = xfin[5] * (1.0f / (float)CH);
        float var = xfin[6] * (1.0f / (float)CH) - mu * mu;
        float inv = rsqrtf(var + 1e-5f);
        out[b * 5 + tid] = inv * xfin[tid] - inv * mu * g_clsA[tid] + g_clsB[tid];
    }
}

extern "C" void kernel_launch(void* const* d_in, const int* in_sizes, int n_in,
                              void* d_out, int out_size) {
    const float* x    = (const float*)d_in[0];
    const float* w1a  = (const float*)d_in[1];
    const float* b1a  = (const float*)d_in[2];
    const float* w2a  = (const float*)d_in[3];
    const float* b2a  = (const float*)d_in[4];
    const float* w1b  = (const float*)d_in[5];
    const float* b1b  = (const float*)d_in[6];
    const float* w2b  = (const float*)d_in[7];
    const float* b2b  = (const float*)d_in[8];
    const float* lng  = (const float*)d_in[9];
    const float* lnb  = (const float*)d_in[10];
    const float* clsw = (const float*)d_in[11];
    const float* clsb = (const float*)d_in[12];
    float* out = (float*)d_out;

    static_assert(SM_BYTES < 227000, "smem over limit");
    cudaFuncSetAttribute(coatgft_kernel,
                         cudaFuncAttributeMaxDynamicSharedMemorySize, SM_BYTES);

    convert_weights_kernel<<<(MID * CH + 255) / 256, 256>>>(
        w1a, w2a, w1b, w2b, clsw, lng, lnb, clsb);
    coatgft_kernel<<<BATCH, THREADS, SM_BYTES>>>(x, b1a, b2a, b1b, b2b, out);
}